// round 14
// baseline (speedup 1.0000x reference)
#include <cuda_runtime.h>

#define NTHR 128
#define HALO 2048
#define SIG_FLOATS (2 * HALO + 8192)                 // 12288
#define BIN_FLOATS (NTHR * 9)                        // 1152
#define SMEM_BYTES ((SIG_FLOATS + BIN_FLOATS) * 4)   // 53760 B

__device__ __forceinline__ float2 ffma2(float2 a, float2 b, float2 c) {
    float2 d;
    asm("fma.rn.f32x2 %0, %1, %2, %3;"
        : "=l"(reinterpret_cast<unsigned long long&>(d))
        : "l"(reinterpret_cast<unsigned long long&>(a)),
          "l"(reinterpret_cast<unsigned long long&>(b)),
          "l"(reinterpret_cast<unsigned long long&>(c)));
    return d;
}
__device__ __forceinline__ float2 fmul2(float2 a, float2 b) {
    float2 d;
    asm("mul.rn.f32x2 %0, %1, %2;"
        : "=l"(reinterpret_cast<unsigned long long&>(d))
        : "l"(reinterpret_cast<unsigned long long&>(a)),
          "l"(reinterpret_cast<unsigned long long&>(b)));
    return d;
}
__device__ __forceinline__ float2 fdup(float x) { return make_float2(x, x); }

// epilogue for ONE position; zp[i] = (z_{k=2i}, z_{k=2i+1})
// LSB index embedding; FMNMX trees; indexed-smem max acc; shift min counter
__device__ __forceinline__ void epi_pos(const float2 zp[4], bool valid,
                                        float* __restrict__ mybins,
                                        unsigned long long& cnt)
{
    float f[8];
#pragma unroll
    for (int i = 0; i < 4; i++) {
        f[2 * i]     = __uint_as_float((__float_as_uint(zp[i].x) & ~7u) | (unsigned)(2 * i));
        f[2 * i + 1] = __uint_as_float((__float_as_uint(zp[i].y) & ~7u) | (unsigned)(2 * i + 1));
    }
    float m = fmaxf(fmaxf(fmaxf(f[0], f[1]), fmaxf(f[2], f[3])),
                    fmaxf(fmaxf(f[4], f[5]), fmaxf(f[6], f[7])));
    float n = fminf(fminf(fminf(f[0], f[1]), fminf(f[2], f[3])),
                    fminf(fminf(f[4], f[5]), fminf(f[6], f[7])));
    if (valid) {
        mybins[__float_as_uint(m) & 7u] += m;
        cnt += 1ull << (8u * (__float_as_uint(n) & 7u));
    }
}

// d > 1 main loop: HD = d/2 compile-time -> immediate LDS offsets
template <int HD>
__device__ __forceinline__ void conv_loop(const float2* __restrict__ A2,
                                          const float2 wp2[36], int tid, int nPos,
                                          float* __restrict__ mybins,
                                          unsigned long long& cnt)
{
#pragma unroll 1
    for (int t = 0; t < 32; t++) {
        const int p = t * 128 + tid;
        float2 za[4], zb[4];
        // r = 0: initialize via packed mul (no zero-init MOVs)
        {
            const float2 v = A2[1024 + p - 4 * HD];
            const float2 d0 = fdup(v.x);
            const float2 d1 = fdup(v.y);
#pragma unroll
            for (int i = 0; i < 4; i++) {
                za[i] = fmul2(wp2[i], d0);
                zb[i] = fmul2(wp2[i], d1);
            }
        }
#pragma unroll
        for (int r = 1; r < 9; r++) {
            const float2 v = A2[1024 + p + (r - 4) * HD];
            const float2 d0 = fdup(v.x);
            const float2 d1 = fdup(v.y);
#pragma unroll
            for (int i = 0; i < 4; i++) {
                za[i] = ffma2(wp2[r * 4 + i], d0, za[i]);
                zb[i] = ffma2(wp2[r * 4 + i], d1, zb[i]);
            }
        }
        epi_pos(za, true, mybins, cnt);
        epi_pos(zb, (2 * p + 1) < nPos, mybins, cnt);
    }
}

// d == 1 main loop: 10 consecutive scalars via 5 aligned LDS.64
__device__ __forceinline__ void conv_loop1(const float2* __restrict__ A2,
                                           const float2 wp2[36], int tid, int nPos,
                                           float* __restrict__ mybins,
                                           unsigned long long& cnt)
{
#pragma unroll 1
    for (int t = 0; t < 32; t++) {
        const int p = t * 128 + tid;
        float a[10];
        {
            float2 v0 = A2[1022 + p], v1 = A2[1023 + p], v2 = A2[1024 + p],
                   v3 = A2[1025 + p], v4 = A2[1026 + p];
            a[0] = v0.x; a[1] = v0.y; a[2] = v1.x; a[3] = v1.y; a[4] = v2.x;
            a[5] = v2.y; a[6] = v3.x; a[7] = v3.y; a[8] = v4.x; a[9] = v4.y;
        }
        float2 za[4], zb[4];
        {
            const float2 d0 = fdup(a[0]);
            const float2 d1 = fdup(a[1]);
#pragma unroll
            for (int i = 0; i < 4; i++) {
                za[i] = fmul2(wp2[i], d0);
                zb[i] = fmul2(wp2[i], d1);
            }
        }
#pragma unroll
        for (int r = 1; r < 9; r++) {
            const float2 d0 = fdup(a[r]);
            const float2 d1 = fdup(a[r + 1]);
#pragma unroll
            for (int i = 0; i < 4; i++) {
                za[i] = ffma2(wp2[r * 4 + i], d0, za[i]);
                zb[i] = ffma2(wp2[r * 4 + i], d1, zb[i]);
            }
        }
        epi_pos(za, true, mybins, cnt);
        epi_pos(zb, (2 * p + 1) < nPos, mybins, cnt);
    }
}

__global__ __launch_bounds__(NTHR, 4)
void hydra_kernel(const float* __restrict__ X, const float* __restrict__ W,
                  const int* __restrict__ I, float* __restrict__ out)
{
    extern __shared__ float sm[];
    float*        A    = sm;
    float*        BINS = sm + SIG_FLOATS;
    float4*       A4   = (float4*)A;
    const float2* A2   = (const float2*)A;

    const int bid = blockIdx.x;
    const int g   = bid & 31;
    const int j   = (bid >> 5) & 1;
    const int di  = (bid >> 6) % 10;
    const int b   = bid / 640;
    const int tid = threadIdx.x;

    // ---- zero halos + bins (gather overwrites the interior) ----
#pragma unroll
    for (int i = tid; i < 512; i += NTHR) {
        A4[i] = make_float4(0.f, 0.f, 0.f, 0.f);
        A4[(HALO + 8192) / 4 + i] = make_float4(0.f, 0.f, 0.f, 0.f);
    }
#pragma unroll
    for (int i = 0; i < 9; i++) BINS[tid * 9 + i] = 0.f;
    float* const mybins = BINS + tid * 9;

    // ---- weights -> registers, k-pair packed: wp2[r*4+i] = (w_{2i,r}, w_{2i+1,r}) ----
    const float* Wb = W + ((di * 2 + j) * 256 + g * 8) * 9;
    float2 wp2[36];
#pragma unroll
    for (int r = 0; r < 9; r++)
#pragma unroll
        for (int i = 0; i < 4; i++)
            wp2[r * 4 + i] = make_float2(__ldg(Wb + (2 * i) * 9 + r),
                                         __ldg(Wb + (2 * i + 1) * 9 + r));

    const int* Ib = I + ((di * 2 + j) * 32 + g) * 6;
    const int ic0 = Ib[0], ic1 = Ib[1], ic2 = Ib[2], ic3 = Ib[3], ic4 = Ib[4], ic5 = Ib[5];

    __syncthreads();

    // ---- channel-gather sum into interior [HALO, HALO+8192) ----
    const float4* X4 = (const float4*)X;
    const int rb = b * 12 * 2048;
#pragma unroll 2
    for (int t = tid; t < 2048; t += NTHR) {
        float4 s = X4[rb + ic0 * 2048 + t];
        float4 v;
        v = X4[rb + ic1 * 2048 + t]; s.x += v.x; s.y += v.y; s.z += v.z; s.w += v.w;
        v = X4[rb + ic2 * 2048 + t]; s.x += v.x; s.y += v.y; s.z += v.z; s.w += v.w;
        v = X4[rb + ic3 * 2048 + t]; s.x += v.x; s.y += v.y; s.z += v.z; s.w += v.w;
        v = X4[rb + ic4 * 2048 + t]; s.x += v.x; s.y += v.y; s.z += v.z; s.w += v.w;
        v = X4[rb + ic5 * 2048 + t]; s.x += v.x; s.y += v.y; s.z += v.z; s.w += v.w;
        A4[HALO / 4 + t] = s;
    }
    __syncthreads();

    // ---- j==1: in-place first difference, 2 barriers ----
    int nPos = 8192;
    if (j == 1) {
        nPos = 8191;
        const int cbase = HALO + tid * 64;
        const float bnd = A[cbase + 64];       // tid==127 reads right-halo zero
        __syncthreads();
        float4* C4 = (float4*)(A + cbase);
        float4 v = C4[0];
#pragma unroll
        for (int i4 = 0; i4 < 16; i4++) {
            float4 vn;
            if (i4 < 15) vn = C4[i4 + 1];
            else         vn = make_float4(bnd, 0.f, 0.f, 0.f);
            float4 o;
            o.x = v.y - v.x; o.y = v.z - v.y; o.z = v.w - v.z; o.w = vn.x - v.w;
            C4[i4] = o;
            v = vn;
        }
        if (tid == NTHR - 1) A[HALO + 8191] = 0.f;
        __syncthreads();
    }

    // ---- main loop, dilation-specialized ----
    unsigned long long cnt = 0ull;

    switch (di) {
        case 0: conv_loop1     (A2, wp2, tid, nPos, mybins, cnt); break;
        case 1: conv_loop<1>   (A2, wp2, tid, nPos, mybins, cnt); break;
        case 2: conv_loop<2>   (A2, wp2, tid, nPos, mybins, cnt); break;
        case 3: conv_loop<4>   (A2, wp2, tid, nPos, mybins, cnt); break;
        case 4: conv_loop<8>   (A2, wp2, tid, nPos, mybins, cnt); break;
        case 5: conv_loop<16>  (A2, wp2, tid, nPos, mybins, cnt); break;
        case 6: conv_loop<32>  (A2, wp2, tid, nPos, mybins, cnt); break;
        case 7: conv_loop<64>  (A2, wp2, tid, nPos, mybins, cnt); break;
        case 8: conv_loop<128> (A2, wp2, tid, nPos, mybins, cnt); break;
        default: conv_loop<256>(A2, wp2, tid, nPos, mybins, cnt); break;
    }

    // ---- block reduction (signal smem reused as scratch) ----
    __syncthreads();
    if (tid < 16) ((unsigned*)A)[tid] = 0u;
    __syncthreads();

    const int lane = tid & 31;
#pragma unroll
    for (int k = 0; k < 8; k++) {
        float v = mybins[k];
        int   c = (int)((cnt >> (8 * k)) & 0xFFull);
#pragma unroll
        for (int off = 16; off; off >>= 1) {
            v += __shfl_down_sync(0xffffffffu, v, off);
            c += __shfl_down_sync(0xffffffffu, c, off);
        }
        if (lane == 0) {
            atomicAdd(&A[k], v);
            atomicAdd((int*)A + 8 + k, c);
        }
    }
    __syncthreads();

    // ---- outputs ----
    const int rowBase = ((di * 2 + j) * 2) * 32 + g;
    if (tid < 8) {
        float v = A[tid];
        out[(b * 1280 + rowBase) * 8 + tid] = v > 0.f ? v : 0.f;
    } else if (tid < 16) {
        const int k = tid - 8;
        const int c = ((const int*)A)[8 + k];
        out[(b * 1280 + rowBase + 32) * 8 + k] = (float)c;
    }
}

extern "C" void kernel_launch(void* const* d_in, const int* in_sizes, int n_in,
                              void* d_out, int out_size)
{
    const float* X = (const float*)d_in[0];
    const float* W = (const float*)d_in[1];
    const int*   I = (const int*)d_in[2];
    float*       O = (float*)d_out;

    cudaFuncSetAttribute(hydra_kernel, cudaFuncAttributeMaxDynamicSharedMemorySize, SMEM_BYTES);
    hydra_kernel<<<20480, NTHR, SMEM_BYTES>>>(X, W, I, O);
}

// round 15
// speedup vs baseline: 1.0002x; 1.0002x over previous
#include <cuda_runtime.h>

#define NTHR 128
#define HALO 2048
#define SIG_FLOATS (2 * HALO + 8192)                 // 12288
#define BIN_FLOATS (NTHR * 9)                        // 1152
#define SMEM_BYTES ((SIG_FLOATS + BIN_FLOATS) * 4)   // 53760 B

__device__ __forceinline__ float2 ffma2(float2 a, float2 b, float2 c) {
    float2 d;
    asm("fma.rn.f32x2 %0, %1, %2, %3;"
        : "=l"(reinterpret_cast<unsigned long long&>(d))
        : "l"(reinterpret_cast<unsigned long long&>(a)),
          "l"(reinterpret_cast<unsigned long long&>(b)),
          "l"(reinterpret_cast<unsigned long long&>(c)));
    return d;
}
__device__ __forceinline__ float2 fmul2(float2 a, float2 b) {
    float2 d;
    asm("mul.rn.f32x2 %0, %1, %2;"
        : "=l"(reinterpret_cast<unsigned long long&>(d))
        : "l"(reinterpret_cast<unsigned long long&>(a)),
          "l"(reinterpret_cast<unsigned long long&>(b)));
    return d;
}
__device__ __forceinline__ float2 fdup(float x) { return make_float2(x, x); }

// epilogue for ONE position; zp[i] = (z_{k=2i}, z_{k=2i+1})
// LSB index embedding; FMNMX trees; indexed-smem max acc; shift min counter
__device__ __forceinline__ void epi_pos(const float2 zp[4], bool valid,
                                        float* __restrict__ mybins,
                                        unsigned long long& cnt)
{
    float f[8];
#pragma unroll
    for (int i = 0; i < 4; i++) {
        f[2 * i]     = __uint_as_float((__float_as_uint(zp[i].x) & ~7u) | (unsigned)(2 * i));
        f[2 * i + 1] = __uint_as_float((__float_as_uint(zp[i].y) & ~7u) | (unsigned)(2 * i + 1));
    }
    float m = fmaxf(fmaxf(fmaxf(f[0], f[1]), fmaxf(f[2], f[3])),
                    fmaxf(fmaxf(f[4], f[5]), fmaxf(f[6], f[7])));
    float n = fminf(fminf(fminf(f[0], f[1]), fminf(f[2], f[3])),
                    fminf(fminf(f[4], f[5]), fminf(f[6], f[7])));
    if (valid) {
        mybins[__float_as_uint(m) & 7u] += m;
        cnt += 1ull << (8u * (__float_as_uint(n) & 7u));
    }
}

// d > 1 main loop: HD = d/2 compile-time -> immediate LDS offsets
template <int HD>
__device__ __forceinline__ void conv_loop(const float2* __restrict__ A2,
                                          const float2 wp2[36], int tid, int nPos,
                                          float* __restrict__ mybins,
                                          unsigned long long& cnt)
{
#pragma unroll 1
    for (int t = 0; t < 32; t++) {
        const int p = t * 128 + tid;
        float2 za[4], zb[4];
        // r = 0: initialize via packed mul (no zero-init MOVs)
        {
            const float2 v = A2[1024 + p - 4 * HD];
            const float2 d0 = fdup(v.x);
            const float2 d1 = fdup(v.y);
#pragma unroll
            for (int i = 0; i < 4; i++) {
                za[i] = fmul2(wp2[i], d0);
                zb[i] = fmul2(wp2[i], d1);
            }
        }
#pragma unroll
        for (int r = 1; r < 9; r++) {
            const float2 v = A2[1024 + p + (r - 4) * HD];
            const float2 d0 = fdup(v.x);
            const float2 d1 = fdup(v.y);
#pragma unroll
            for (int i = 0; i < 4; i++) {
                za[i] = ffma2(wp2[r * 4 + i], d0, za[i]);
                zb[i] = ffma2(wp2[r * 4 + i], d1, zb[i]);
            }
        }
        epi_pos(za, true, mybins, cnt);
        epi_pos(zb, (2 * p + 1) < nPos, mybins, cnt);
    }
}

// d == 1 main loop: 10 consecutive scalars via 5 aligned LDS.64
__device__ __forceinline__ void conv_loop1(const float2* __restrict__ A2,
                                           const float2 wp2[36], int tid, int nPos,
                                           float* __restrict__ mybins,
                                           unsigned long long& cnt)
{
#pragma unroll 1
    for (int t = 0; t < 32; t++) {
        const int p = t * 128 + tid;
        float a[10];
        {
            float2 v0 = A2[1022 + p], v1 = A2[1023 + p], v2 = A2[1024 + p],
                   v3 = A2[1025 + p], v4 = A2[1026 + p];
            a[0] = v0.x; a[1] = v0.y; a[2] = v1.x; a[3] = v1.y; a[4] = v2.x;
            a[5] = v2.y; a[6] = v3.x; a[7] = v3.y; a[8] = v4.x; a[9] = v4.y;
        }
        float2 za[4], zb[4];
        {
            const float2 d0 = fdup(a[0]);
            const float2 d1 = fdup(a[1]);
#pragma unroll
            for (int i = 0; i < 4; i++) {
                za[i] = fmul2(wp2[i], d0);
                zb[i] = fmul2(wp2[i], d1);
            }
        }
#pragma unroll
        for (int r = 1; r < 9; r++) {
            const float2 d0 = fdup(a[r]);
            const float2 d1 = fdup(a[r + 1]);
#pragma unroll
            for (int i = 0; i < 4; i++) {
                za[i] = ffma2(wp2[r * 4 + i], d0, za[i]);
                zb[i] = ffma2(wp2[r * 4 + i], d1, zb[i]);
            }
        }
        epi_pos(za, true, mybins, cnt);
        epi_pos(zb, (2 * p + 1) < nPos, mybins, cnt);
    }
}

__global__ __launch_bounds__(NTHR, 4)
void hydra_kernel(const float* __restrict__ X, const float* __restrict__ W,
                  const int* __restrict__ I, float* __restrict__ out)
{
    extern __shared__ float sm[];
    float*        A    = sm;
    float*        BINS = sm + SIG_FLOATS;
    float4*       A4   = (float4*)A;
    const float2* A2   = (const float2*)A;

    const int bid = blockIdx.x;
    const int g   = bid & 31;
    const int j   = (bid >> 5) & 1;
    const int di  = (bid >> 6) % 10;
    const int b   = bid / 640;
    const int tid = threadIdx.x;

    // ---- zero halos + bins (gather overwrites the interior) ----
#pragma unroll
    for (int i = tid; i < 512; i += NTHR) {
        A4[i] = make_float4(0.f, 0.f, 0.f, 0.f);
        A4[(HALO + 8192) / 4 + i] = make_float4(0.f, 0.f, 0.f, 0.f);
    }
#pragma unroll
    for (int i = 0; i < 9; i++) BINS[tid * 9 + i] = 0.f;
    float* const mybins = BINS + tid * 9;

    // ---- weights -> registers, k-pair packed: wp2[r*4+i] = (w_{2i,r}, w_{2i+1,r}) ----
    const float* Wb = W + ((di * 2 + j) * 256 + g * 8) * 9;
    float2 wp2[36];
#pragma unroll
    for (int r = 0; r < 9; r++)
#pragma unroll
        for (int i = 0; i < 4; i++)
            wp2[r * 4 + i] = make_float2(__ldg(Wb + (2 * i) * 9 + r),
                                         __ldg(Wb + (2 * i + 1) * 9 + r));

    const int* Ib = I + ((di * 2 + j) * 32 + g) * 6;
    const int ic0 = Ib[0], ic1 = Ib[1], ic2 = Ib[2], ic3 = Ib[3], ic4 = Ib[4], ic5 = Ib[5];

    __syncthreads();

    // ---- channel-gather sum into interior [HALO, HALO+8192) ----
    const float4* X4 = (const float4*)X;
    const int rb = b * 12 * 2048;
#pragma unroll 2
    for (int t = tid; t < 2048; t += NTHR) {
        float4 s = X4[rb + ic0 * 2048 + t];
        float4 v;
        v = X4[rb + ic1 * 2048 + t]; s.x += v.x; s.y += v.y; s.z += v.z; s.w += v.w;
        v = X4[rb + ic2 * 2048 + t]; s.x += v.x; s.y += v.y; s.z += v.z; s.w += v.w;
        v = X4[rb + ic3 * 2048 + t]; s.x += v.x; s.y += v.y; s.z += v.z; s.w += v.w;
        v = X4[rb + ic4 * 2048 + t]; s.x += v.x; s.y += v.y; s.z += v.z; s.w += v.w;
        v = X4[rb + ic5 * 2048 + t]; s.x += v.x; s.y += v.y; s.z += v.z; s.w += v.w;
        A4[HALO / 4 + t] = s;
    }
    __syncthreads();

    // ---- j==1: in-place first difference, 2 barriers ----
    int nPos = 8192;
    if (j == 1) {
        nPos = 8191;
        const int cbase = HALO + tid * 64;
        const float bnd = A[cbase + 64];       // tid==127 reads right-halo zero
        __syncthreads();
        float4* C4 = (float4*)(A + cbase);
        float4 v = C4[0];
#pragma unroll
        for (int i4 = 0; i4 < 16; i4++) {
            float4 vn;
            if (i4 < 15) vn = C4[i4 + 1];
            else         vn = make_float4(bnd, 0.f, 0.f, 0.f);
            float4 o;
            o.x = v.y - v.x; o.y = v.z - v.y; o.z = v.w - v.z; o.w = vn.x - v.w;
            C4[i4] = o;
            v = vn;
        }
        if (tid == NTHR - 1) A[HALO + 8191] = 0.f;
        __syncthreads();
    }

    // ---- main loop, dilation-specialized ----
    unsigned long long cnt = 0ull;

    switch (di) {
        case 0: conv_loop1     (A2, wp2, tid, nPos, mybins, cnt); break;
        case 1: conv_loop<1>   (A2, wp2, tid, nPos, mybins, cnt); break;
        case 2: conv_loop<2>   (A2, wp2, tid, nPos, mybins, cnt); break;
        case 3: conv_loop<4>   (A2, wp2, tid, nPos, mybins, cnt); break;
        case 4: conv_loop<8>   (A2, wp2, tid, nPos, mybins, cnt); break;
        case 5: conv_loop<16>  (A2, wp2, tid, nPos, mybins, cnt); break;
        case 6: conv_loop<32>  (A2, wp2, tid, nPos, mybins, cnt); break;
        case 7: conv_loop<64>  (A2, wp2, tid, nPos, mybins, cnt); break;
        case 8: conv_loop<128> (A2, wp2, tid, nPos, mybins, cnt); break;
        default: conv_loop<256>(A2, wp2, tid, nPos, mybins, cnt); break;
    }

    // ---- block reduction (signal smem reused as scratch) ----
    __syncthreads();
    if (tid < 16) ((unsigned*)A)[tid] = 0u;
    __syncthreads();

    const int lane = tid & 31;
#pragma unroll
    for (int k = 0; k < 8; k++) {
        float v = mybins[k];
        int   c = (int)((cnt >> (8 * k)) & 0xFFull);
#pragma unroll
        for (int off = 16; off; off >>= 1) {
            v += __shfl_down_sync(0xffffffffu, v, off);
            c += __shfl_down_sync(0xffffffffu, c, off);
        }
        if (lane == 0) {
            atomicAdd(&A[k], v);
            atomicAdd((int*)A + 8 + k, c);
        }
    }
    __syncthreads();

    // ---- outputs ----
    const int rowBase = ((di * 2 + j) * 2) * 32 + g;
    if (tid < 8) {
        float v = A[tid];
        out[(b * 1280 + rowBase) * 8 + tid] = v > 0.f ? v : 0.f;
    } else if (tid < 16) {
        const int k = tid - 8;
        const int c = ((const int*)A)[8 + k];
        out[(b * 1280 + rowBase + 32) * 8 + k] = (float)c;
    }
}

extern "C" void kernel_launch(void* const* d_in, const int* in_sizes, int n_in,
                              void* d_out, int out_size)
{
    const float* X = (const float*)d_in[0];
    const float* W = (const float*)d_in[1];
    const int*   I = (const int*)d_in[2];
    float*       O = (float*)d_out;

    cudaFuncSetAttribute(hydra_kernel, cudaFuncAttributeMaxDynamicSharedMemorySize, SMEM_BYTES);
    hydra_kernel<<<20480, NTHR, SMEM_BYTES>>>(X, W, I, O);
}